// round 13
// baseline (speedup 1.0000x reference)
#include <cuda_runtime.h>
#include <cuda_bf16.h>
#include <cuda_fp16.h>
#include <math.h>
#include <stdint.h>

// ---------------- constants ----------------
#define BB   16
#define NN_  512
#define LL   1024
#define CD   128
#define GD   64
#define NH   4
#define LAT  128

// ---------------- scratch ----------------
__device__ float g_av       [BB*NN_*CD];
__device__ float g_wh1      [BB*NN_*(GD*NH)];
__device__ float g_multi    [BB*NN_*(GD*NH)];
__device__ float g_wh2      [BB*NN_*CD];
__device__ float g_x        [BB*NN_*CD];
__device__ float g_atoms_vec[BB*NN_*LAT];
__device__ float g_av_att   [BB*NN_*LAT];
__device__ float g_src1[BB*NH*NN_], g_dst1[BB*NH*NN_];
__device__ float g_src2[BB*NN_],    g_dst2[BB*NN_];
__device__ float g_cnvA[BB*LL*CD];
__device__ float g_cnvB[BB*LL*CD];
__device__ float g_T[30*11*CD];
__device__ float g_WcatT[256*128];
__device__ float g_WgoT [128*256];
__device__ float g_pp [BB*8*128];
__device__ float g_pm [BB*8];
__device__ float g_pp2[BB*8*128];
__device__ float g_pm2[BB*8];
__device__ uint32_t g_adjmask[BB*NN_*16];

__device__ __forceinline__ float lrelu(float x){ return x > 0.f ? x : 0.2f*x; }
__device__ __forceinline__ float eluf (float x){ return x > 0.f ? x : (__expf(x) - 1.f); }

// ---------------- f32x2 packed helpers (conv) ----------------
__device__ __forceinline__ uint64_t pk2(float x){
    uint32_t xi = __float_as_uint(x);
    uint64_t r; asm("mov.b64 %0, {%1, %1};" : "=l"(r) : "r"(xi)); return r;
}
__device__ __forceinline__ uint64_t pk2f(float x, float y){
    uint32_t xi = __float_as_uint(x), yi = __float_as_uint(y);
    uint64_t r; asm("mov.b64 %0, {%1, %2};" : "=l"(r) : "r"(xi), "r"(yi)); return r;
}
__device__ __forceinline__ void fma2(uint64_t& d, uint64_t a, uint64_t b){
    asm("fma.rn.f32x2 %0, %1, %2, %0;" : "+l"(d) : "l"(a), "l"(b));
}
__device__ __forceinline__ float2 up2(uint64_t v){
    uint32_t lo, hi; asm("mov.b64 {%0, %1}, %2;" : "=r"(lo), "=r"(hi) : "l"(v));
    return make_float2(__uint_as_float(lo), __uint_as_float(hi));
}

// ---------------- bf16 helpers (k_mm) ----------------
__device__ __forceinline__ void split2(float x, float y, uint32_t& hi, uint32_t& lo){
    __nv_bfloat162 h = __floats2bfloat162_rn(x, y);
    float hx = __bfloat162float(h.x), hy = __bfloat162float(h.y);
    __nv_bfloat162 l = __floats2bfloat162_rn(x - hx, y - hy);
    hi = *(uint32_t*)&h; lo = *(uint32_t*)&l;
}
__device__ __forceinline__ void mma16816(float* d, const uint32_t* a, const uint32_t* b){
    asm volatile(
        "mma.sync.aligned.m16n8k16.row.col.f32.bf16.bf16.f32 "
        "{%0,%1,%2,%3},{%4,%5,%6,%7},{%8,%9},{%0,%1,%2,%3};"
        : "+f"(d[0]), "+f"(d[1]), "+f"(d[2]), "+f"(d[3])
        : "r"(a[0]), "r"(a[1]), "r"(a[2]), "r"(a[3]), "r"(b[0]), "r"(b[1]));
}

// ---------------- fp16 helpers (attention) ----------------
__device__ __forceinline__ uint32_t packhf2(float x, float y){
    __half2 h = __floats2half2_rn(x, y);
    return *(uint32_t*)&h;
}
__device__ __forceinline__ uint32_t hadd2uh(uint32_t a, uint32_t b){
    __half2 r = __hadd2(*(__half2*)&a, *(__half2*)&b);
    return *(uint32_t*)&r;
}
__device__ __forceinline__ uint32_t hmul2uh(uint32_t a, uint32_t b){
    __half2 r = __hmul2(*(__half2*)&a, *(__half2*)&b);
    return *(uint32_t*)&r;
}
__device__ __forceinline__ float2 h2f2(uint32_t w){
    return __half22float2(*(__half2*)&w);
}
__device__ __forceinline__ void mma16816h(float* d, const uint32_t* a, const uint32_t* b){
    asm volatile(
        "mma.sync.aligned.m16n8k16.row.col.f32.f16.f16.f32 "
        "{%0,%1,%2,%3},{%4,%5,%6,%7},{%8,%9},{%0,%1,%2,%3};"
        : "+f"(d[0]), "+f"(d[1]), "+f"(d[2]), "+f"(d[3])
        : "r"(a[0]), "r"(a[1]), "r"(a[2]), "r"(a[3]), "r"(b[0]), "r"(b[1]));
}

// ---------------- fused prep kernel ----------------
__global__ void __launch_bounds__(256) k_prep(
    const int* __restrict__ adj, const float* __restrict__ W_gat,
    const float* __restrict__ W_go, const float* __restrict__ conv_w,
    const float* __restrict__ E_amino, const int* __restrict__ atoms,
    const float* __restrict__ E_atom)
{
    const int bid = blockIdx.x, tid = threadIdx.x;
    if (bid < 16384) {
        int t = bid*256 + tid;
        uint32_t bal = __ballot_sync(0xffffffffu, adj[t] > 0);
        if ((t & 31) == 0) g_adjmask[t >> 5] = bal;
    } else if (bid < 16512) {
        int idx = (bid - 16384)*256 + tid;
        int n = idx >> 7, k = idx & 127;
        int h = n >> 6, f = n & 63;
        g_WcatT[n*128 + k] = W_gat[((h*128) + k)*64 + f];
    } else if (bid < 16640) {
        int idx = (bid - 16512)*256 + tid;
        int n = idx >> 8, k = idx & 255;
        g_WgoT[n*256 + k] = W_go[k*128 + n];
    } else if (bid < 16805) {
        int idx = (bid - 16640)*256 + tid;
        if (idx < 42240) {
            int f = idx & 127, rest = idx >> 7;
            int dl = rest % 11, a = rest / 11;
            float acc = 0.f;
            #pragma unroll
            for (int df = 0; df < 11; ++df) {
                int fi = f + df - 5;
                if (fi >= 0 && fi < 128) acc += conv_w[dl*11 + df] * E_amino[a*128 + fi];
            }
            g_T[(a*11 + dl)*128 + f] = acc;
        }
    } else {
        int idx = (bid - 16805)*256 + tid;
        int row = idx >> 7, f = idx & 127;
        g_av[(size_t)row*128 + f] = E_atom[atoms[row]*128 + f];
    }
}

// ---------------- bf16-split tensor GEMM (64x64 tiles) ----------------
template<int ACT>
__global__ void __launch_bounds__(256) k_mm(
    const float* __restrict__ A, const float* __restrict__ BT,
    const float* __restrict__ bias, float* __restrict__ C,
    int M, int N, int K)
{
    __shared__ uint32_t Ah[2304], Al[2304], Bh[2304], Bl[2304];

    const int m0 = blockIdx.x*64, n0 = blockIdx.y*64;
    const int tid = threadIdx.x, w = tid >> 5, lane = tid & 31;
    const int wm = w & 3, wn = w >> 2;
    const int r4 = lane >> 2, cl = lane & 3;

    float acc[4][4];
    #pragma unroll
    for (int j = 0; j < 4; ++j)
        #pragma unroll
        for (int q = 0; q < 4; ++q) acc[j][q] = 0.f;

    for (int k0 = 0; k0 < K; k0 += 64) {
        __syncthreads();
        #pragma unroll
        for (int s = tid; s < 1024; s += 256) {
            int r = s >> 4, q = s & 15;
            float4 v = *(const float4*)&A[(size_t)(m0+r)*K + k0 + q*4];
            uint32_t h0,l0,h1,l1;
            split2(v.x, v.y, h0, l0); split2(v.z, v.w, h1, l1);
            int off = r*36 + q*2;
            Ah[off] = h0; Ah[off+1] = h1;
            Al[off] = l0; Al[off+1] = l1;
            float4 bv = *(const float4*)&BT[(size_t)(n0+r)*K + k0 + q*4];
            split2(bv.x, bv.y, h0, l0); split2(bv.z, bv.w, h1, l1);
            Bh[off] = h0; Bh[off+1] = h1;
            Bl[off] = l0; Bl[off+1] = l1;
        }
        __syncthreads();
        #pragma unroll
        for (int kk = 0; kk < 4; ++kk) {
            const int kw = kk*8;
            uint32_t ah[4], al[4];
            {
                int base = (wm*16 + r4)*36 + kw + cl;
                ah[0]=Ah[base];     ah[1]=Ah[base+288];
                ah[2]=Ah[base+4];   ah[3]=Ah[base+292];
                al[0]=Al[base];     al[1]=Al[base+288];
                al[2]=Al[base+4];   al[3]=Al[base+292];
            }
            uint32_t bh[4][2], bl[4][2];
            #pragma unroll
            for (int fn = 0; fn < 4; ++fn) {
                int base = (wn*32 + fn*8 + r4)*36 + kw + cl;
                bh[fn][0]=Bh[base]; bh[fn][1]=Bh[base+4];
                bl[fn][0]=Bl[base]; bl[fn][1]=Bl[base+4];
            }
            #pragma unroll
            for (int fn = 0; fn < 4; ++fn) {
                mma16816(acc[fn], ah, bh[fn]);
                mma16816(acc[fn], ah, bl[fn]);
                mma16816(acc[fn], al, bh[fn]);
            }
        }
    }
    #pragma unroll
    for (int fn = 0; fn < 4; ++fn) {
        int row = m0 + wm*16 + r4;
        int col = n0 + wn*32 + fn*8 + 2*cl;
        float b0 = 0.f, b1 = 0.f;
        if (bias) { b0 = bias[col]; b1 = bias[col+1]; }
        float v0 = acc[fn][0] + b0, v1 = acc[fn][1] + b1;
        float v2 = acc[fn][2] + b0, v3 = acc[fn][3] + b1;
        if (ACT) { v0=lrelu(v0); v1=lrelu(v1); v2=lrelu(v2); v3=lrelu(v3); }
        *(float2*)&C[(size_t)row*N + col]     = make_float2(v0, v1);
        *(float2*)&C[(size_t)(row+8)*N + col] = make_float2(v2, v3);
    }
}

// ---------------- GAT attention: fp16, 128-row i-tile, 64-col f-tile, 512 threads ----------------
template<int MH>
__global__ void __launch_bounds__(512) k_attn(
    const float* __restrict__ wh, const float* __restrict__ src,
    const float* __restrict__ dst, const uint32_t* __restrict__ adjmask,
    float* __restrict__ out, int WS)
{
    __shared__ uint32_t Dp[256];
    __shared__ uint32_t PQ[512];
    __shared__ uint32_t sD2[128];
    __shared__ uint32_t sPQ[128];
    __shared__ float Sum[128], pst[512];
    __shared__ uint32_t msk[2048];
    __shared__ uint32_t Ath[2304];
    __shared__ uint32_t Bh[1152], Bl[1152];

    const int it = blockIdx.x, hy = blockIdx.y, b = blockIdx.z;
    const int i0 = it*128;
    const int tid = threadIdx.x, w = tid >> 5, lane = tid & 31;
    const int r4 = lane >> 2, cl = lane & 3;
    const int whoff = hy*64;
    const int sdoff = MH ? (b*NH + hy) : b;

    const float* dstb = dst + (size_t)sdoff*512;
    const float* srcb = src + (size_t)sdoff*512;
    if (tid < 256) {
        float d0 = dstb[2*tid], d1 = dstb[2*tid + 1];
        Dp[tid] = packhf2(d0, d1);
        PQ[2*tid]     = packhf2(__expf(d0), __expf(0.2f*d0));
        PQ[2*tid + 1] = packhf2(__expf(d1), __expf(0.2f*d1));
    }
    if (tid < 128) {
        float s = srcb[i0 + tid];
        sD2[tid] = packhf2(s, s);
        sPQ[tid] = packhf2(__expf(s), __expf(0.2f*s));
    }
    {
        const uint32_t* mb = adjmask + ((size_t)(b*512) + i0)*16;
        for (int s = tid; s < 2048; s += 512) msk[s] = mb[s];
    }

    const int wm = w & 3, wn = w >> 2;
    float acc[2][2][4];
    #pragma unroll
    for (int i = 0; i < 2; ++i)
        #pragma unroll
        for (int j = 0; j < 2; ++j)
            #pragma unroll
            for (int q = 0; q < 4; ++q) acc[i][j][q] = 0.f;

    const int ai = tid >> 2, qt = tid & 3;
    __syncthreads();
    const uint32_t si2 = sD2[ai], piq = sPQ[ai];
    float ps = 0.f;

    for (int c = 0; c < 16; ++c) {
        const int j0 = c*32;
        if (c) __syncthreads();
        {
            uint32_t mw = msk[ai*16 + c];
            #pragma unroll
            for (int jp = 0; jp < 4; ++jp) {
                int jl0 = qt*8 + jp*2, jl1 = jl0 + 1;
                uint32_t s2 = hadd2uh(si2, Dp[c*16 + qt*4 + jp]);
                uint32_t pr0 = hmul2uh(PQ[j0 + jl0], piq);
                uint32_t pr1 = hmul2uh(PQ[j0 + jl1], piq);
                uint32_t u0 = (s2 & 0x8000u)     ? (pr0 >> 16)          : (pr0 & 0xffffu);
                uint32_t u1 = (s2 & 0x80000000u) ? (pr1 & 0xffff0000u)  : (pr1 << 16);
                if (!((mw >> jl0) & 1u)) u0 = 0;
                if (!((mw >> jl1) & 1u)) u1 = 0;
                uint32_t word = u0 | u1;
                Ath[ai*18 + qt*4 + jp] = word;
                float2 f = h2f2(word);
                ps += f.x + f.y;
            }
        }
        {
            const int f = tid & 63, jg = tid >> 6;
            #pragma unroll
            for (int p = 0; p < 2; ++p) {
                int jl = jg*4 + p*2;
                float v0 = wh[(size_t)(b*512 + j0 + jl)*WS + whoff + f];
                float v1 = wh[(size_t)(b*512 + j0 + jl + 1)*WS + whoff + f];
                uint32_t hw = packhf2(v0, v1);
                float2 hv = h2f2(hw);
                uint32_t lw = packhf2(v0 - hv.x, v1 - hv.y);
                Bh[f*18 + jg*2 + p] = hw;
                Bl[f*18 + jg*2 + p] = lw;
            }
        }
        __syncthreads();
        #pragma unroll
        for (int kk = 0; kk < 2; ++kk) {
            const int kw = kk*8;
            uint32_t ah[2][4];
            #pragma unroll
            for (int fm = 0; fm < 2; ++fm) {
                int base = (wm*32 + fm*16 + r4)*18 + kw + cl;
                ah[fm][0]=Ath[base];     ah[fm][1]=Ath[base+144];
                ah[fm][2]=Ath[base+4];   ah[fm][3]=Ath[base+148];
            }
            uint32_t bh[2][2], bl[2][2];
            #pragma unroll
            for (int fn = 0; fn < 2; ++fn) {
                int base = (wn*16 + fn*8 + r4)*18 + kw + cl;
                bh[fn][0]=Bh[base]; bh[fn][1]=Bh[base+4];
                bl[fn][0]=Bl[base]; bl[fn][1]=Bl[base+4];
            }
            #pragma unroll
            for (int fm = 0; fm < 2; ++fm)
                #pragma unroll
                for (int fn = 0; fn < 2; ++fn) {
                    mma16816h(acc[fm][fn], ah[fm], bh[fn]);
                    mma16816h(acc[fm][fn], ah[fm], bl[fn]);
                }
        }
    }
    pst[tid] = ps;
    __syncthreads();
    if (tid < 128)
        Sum[tid] = pst[4*tid] + pst[4*tid+1] + pst[4*tid+2] + pst[4*tid+3];
    __syncthreads();
    #pragma unroll
    for (int fm = 0; fm < 2; ++fm) {
        int rl = wm*32 + fm*16 + r4;
        float S0 = Sum[rl],   i0v = (S0 > 0.f) ? 1.f/S0 : 0.f;
        float S1 = Sum[rl+8], i1v = (S1 > 0.f) ? 1.f/S1 : 0.f;
        #pragma unroll
        for (int fn = 0; fn < 2; ++fn) {
            int col = whoff + wn*16 + fn*8 + 2*cl;
            float v0 = eluf(acc[fm][fn][0] * i0v);
            float v1 = eluf(acc[fm][fn][1] * i0v);
            float v2 = eluf(acc[fm][fn][2] * i1v);
            float v3 = eluf(acc[fm][fn][3] * i1v);
            *(float2*)&out[(size_t)(b*512 + i0 + rl)*WS + col]     = make_float2(v0, v1);
            *(float2*)&out[(size_t)(b*512 + i0 + rl + 8)*WS + col] = make_float2(v2, v3);
        }
    }
}

// ---------------- src/dst score kernels ----------------
__global__ void k_srcdst1(const float* __restrict__ a_gat){
    const int row = blockIdx.x;
    const int b = row >> 9, n = row & 511;
    const int tid = threadIdx.x;
    __shared__ float wrow[256];
    wrow[tid] = g_wh1[(size_t)row*256 + tid];
    __syncthreads();
    const int w = tid >> 5, l = tid & 31;
    const int h = w >> 1, half = w & 1;
    float v = wrow[h*64 + l]      * a_gat[h*128 + half*64 + l]
            + wrow[h*64 + 32 + l] * a_gat[h*128 + half*64 + 32 + l];
    #pragma unroll
    for (int o = 16; o; o >>= 1) v += __shfl_down_sync(0xffffffffu, v, o);
    if (l == 0) {
        float* outp = half ? g_dst1 : g_src1;
        outp[(size_t)(b*4 + h)*512 + n] = v;
    }
}
__global__ void k_srcdst2(const float* __restrict__ a_go){
    const int row = blockIdx.x;
    const int tid = threadIdx.x;
    __shared__ float wrow[128];
    __shared__ float part[4];
    wrow[tid] = g_wh2[(size_t)row*128 + tid];
    __syncthreads();
    const int w = tid >> 5, l = tid & 31;
    const int which = w >> 1, p = w & 1;
    float v = wrow[p*64 + l]      * a_go[which*128 + p*64 + l]
            + wrow[p*64 + 32 + l] * a_go[which*128 + p*64 + 32 + l];
    #pragma unroll
    for (int o = 16; o; o >>= 1) v += __shfl_down_sync(0xffffffffu, v, o);
    if (l == 0) part[w] = v;
    __syncthreads();
    if (tid == 0) g_src2[row] = part[0] + part[1];
    if (tid == 1) g_dst2[row] = part[2] + part[3];
}

// ---------------- CNN ----------------
__global__ void k_conv1(const int* __restrict__ amino, const float* __restrict__ conv_b){
    const int l = blockIdx.x, b = blockIdx.y, f = threadIdx.x;
    float acc = conv_b[0];
    #pragma unroll
    for (int dl = 0; dl < 11; ++dl) {
        int l2 = l + dl - 5;
        if (l2 >= 0 && l2 < 1024) {
            int id = amino[b*1024 + l2];
            acc += g_T[((size_t)id*11 + dl)*128 + f];
        }
    }
    g_cnvA[((size_t)(b*1024) + l)*128 + f] = fmaxf(acc, 0.f);
}

// 11x11 SAME conv; row-major walk with lane-duplicated tile + paired weights.
// Thread owns 2 consecutive output rows x 4 f. Zero packing movs in the inner loop.
__global__ void __launch_bounds__(256) k_conv(
    const float* __restrict__ in, float* __restrict__ out,
    const float* __restrict__ wsrc, const float* __restrict__ bsrc)
{
    __shared__ float2 tile[26*140];       // lane-duplicated values, col f at +5
    __shared__ uint64_t wp[132];          // wp[k*11+df] = (w[k][df], w[k-1][df])
    const int lb = blockIdx.x * 16, b = blockIdx.y;
    const int tid = threadIdx.x;

    for (int idx = tid; idx < 132; idx += 256) {
        int k = idx / 11, df = idx % 11;
        float wa = (k <= 10) ? wsrc[k*11 + df] : 0.f;
        float wb = (k >= 1)  ? wsrc[(k-1)*11 + df] : 0.f;
        wp[idx] = pk2f(wa, wb);
    }
    for (int idx = tid; idx < 832; idx += 256) {         // 26 rows * 32 float4
        int r = idx >> 5, c4 = idx & 31;
        int gl = lb + r - 5;
        float4 v = make_float4(0.f, 0.f, 0.f, 0.f);
        if (gl >= 0 && gl < 1024)
            v = *(const float4*)&in[((size_t)(b*1024) + gl)*128 + c4*4];
        float2* t = &tile[r*140 + 5 + c4*4];
        t[0] = make_float2(v.x, v.x); t[1] = make_float2(v.y, v.y);
        t[2] = make_float2(v.z, v.z); t[3] = make_float2(v.w, v.w);
    }
    for (int idx = tid; idx < 312; idx += 256) {         // border cols 0..4, 133..139
        int r = idx / 12, c = idx % 12;
        tile[r*140 + (c < 5 ? c : 128 + c)] = make_float2(0.f, 0.f);
    }
    __syncthreads();

    const int fg = tid >> 3, lg = tid & 7;
    const int f0 = fg * 4;
    const int rbase = lg * 2;             // output rows lb+rbase, lb+rbase+1

    uint64_t acc[4];
    {
        uint64_t bp = pk2(bsrc[0]);
        acc[0]=bp; acc[1]=bp; acc[2]=bp; acc[3]=bp;
    }
    #pragma unroll
    for (int k = 0; k < 12; ++k) {
        const uint64_t* vrow = (const uint64_t*)&tile[(rbase + k)*140 + f0];
        uint64_t vpv[14];
        #pragma unroll
        for (int j = 0; j < 14; ++j) vpv[j] = vrow[j];
        const uint64_t* wrow = &wp[k*11];
        #pragma unroll
        for (int df = 0; df < 11; ++df) {
            uint64_t wv = wrow[df];
            fma2(acc[0], wv, vpv[df+0]);
            fma2(acc[1], wv, vpv[df+1]);
            fma2(acc[2], wv, vpv[df+2]);
            fma2(acc[3], wv, vpv[df+3]);
        }
    }
    float* o0 = out + ((size_t)(b*1024) + lb + rbase)*128 + f0;
    float* o1 = o0 + 128;
    #pragma unroll
    for (int k = 0; k < 4; ++k) {
        float2 v = up2(acc[k]);
        o0[k] = fmaxf(v.x, 0.f);
        o1[k] = fmaxf(v.y, 0.f);
    }
}

// ---------------- masked mean pooling (partial) ----------------
__global__ void k_mean_part(const float* __restrict__ in, const float* __restrict__ mask,
                            float* __restrict__ pp, float* __restrict__ pm, int NNd){
    const int ch = blockIdx.x, b = blockIdx.y, f = threadIdx.x;
    const int rows = NNd / 8;
    const int r0 = ch * rows;
    float s = 0.f, m = 0.f;
    #pragma unroll 4
    for (int n = r0; n < r0 + rows; ++n) {
        float mk = mask[b*NNd + n];
        m += mk;
        s += mk * in[((size_t)b*NNd + n)*128 + f];
    }
    pp[(size_t)(b*8 + ch)*128 + f] = s;
    if (f == 0) pm[b*8 + ch] = m;
}

// ---------------- final predictor (fused mean-finalize + head) ----------------
__global__ void k_final(const float* __restrict__ pp,  const float* __restrict__ pm,
                        const float* __restrict__ pp2, const float* __restrict__ pm2,
                        const float* __restrict__ pred_w, const float* __restrict__ pred_b,
                        float* __restrict__ out){
    __shared__ float red[256];
    const int b = blockIdx.x, c = threadIdx.x;
    const float* P = (c < 128) ? pp  : pp2;
    const float* M = (c < 128) ? pm  : pm2;
    const int f = c & 127;
    float s = 0.f, m = 0.f;
    #pragma unroll
    for (int ch = 0; ch < 8; ++ch) {
        s += P[(size_t)(b*8 + ch)*128 + f];
        m += M[b*8 + ch];
    }
    float v = s / m;
    v = v > 0.f ? v : 0.04f*v;    // leaky_relu applied twice
    red[c] = v * pred_w[c];
    __syncthreads();
    for (int st = 128; st > 0; st >>= 1) {
        if (c < st) red[c] += red[c + st];
        __syncthreads();
    }
    if (c == 0) out[b] = red[0] + pred_b[0];
}

// ---------------- launch ----------------
extern "C" void kernel_launch(void* const* d_in, const int* in_sizes, int n_in,
                              void* d_out, int out_size)
{
    const int*   atoms      = (const int*)  d_in[0];
    const float* atoms_mask = (const float*)d_in[1];
    const int*   adj        = (const int*)  d_in[2];
    const int*   amino      = (const int*)  d_in[3];
    const float* amino_mask = (const float*)d_in[4];
    const float* E_atom     = (const float*)d_in[5];
    const float* E_amino    = (const float*)d_in[6];
    const float* W_gat      = (const float*)d_in[7];
    const float* a_gat      = (const float*)d_in[8];
    const float* W_go       = (const float*)d_in[9];
    const float* a_go       = (const float*)d_in[10];
    const float* W_comp_w   = (const float*)d_in[11];
    const float* W_comp_b   = (const float*)d_in[12];
    const float* conv_w     = (const float*)d_in[13];
    const float* conv_b     = (const float*)d_in[14];
    const float* W_att_w    = (const float*)d_in[15];
    const float* W_att_b    = (const float*)d_in[16];
    const float* pred_w     = (const float*)d_in[17];
    const float* pred_b     = (const float*)d_in[18];
    float* out = (float*)d_out;

    float *p_WcatT, *p_WgoT;
    float *p_av, *p_wh1, *p_multi, *p_wh2, *p_x, *p_atoms_vec, *p_av_att;
    float *p_cnvA, *p_cnvB;
    float *p_src1, *p_dst1, *p_src2, *p_dst2;
    float *p_pp, *p_pm, *p_pp2, *p_pm2;
    uint32_t* p_adjm;
    cudaGetSymbolAddress((void**)&p_WcatT, g_WcatT);
    cudaGetSymbolAddress((void**)&p_WgoT,  g_WgoT);
    cudaGetSymbolAddress((void**)&p_av,    g_av);
    cudaGetSymbolAddress((void**)&p_wh1,   g_wh1);
    cudaGetSymbolAddress((void**)&p_multi, g_multi);
    cudaGetSymbolAddress((void**)&p_wh2,   g_wh2);
    cudaGetSymbolAddress((void**)&p_x,     g_x);
    cudaGetSymbolAddress((void**)&p_atoms_vec, g_atoms_vec);
    cudaGetSymbolAddress((void**)&p_av_att, g_av_att);
    cudaGetSymbolAddress((void**)&p_src1,  g_src1);
    cudaGetSymbolAddress((void**)&p_dst1,  g_dst1);
    cudaGetSymbolAddress((void**)&p_src2,  g_src2);
    cudaGetSymbolAddress((void**)&p_dst2,  g_dst2);
    cudaGetSymbolAddress((void**)&p_cnvA,  g_cnvA);
    cudaGetSymbolAddress((void**)&p_cnvB,  g_cnvB);
    cudaGetSymbolAddress((void**)&p_pp,    g_pp);
    cudaGetSymbolAddress((void**)&p_pm,    g_pm);
    cudaGetSymbolAddress((void**)&p_pp2,   g_pp2);
    cudaGetSymbolAddress((void**)&p_pm2,   g_pm2);
    cudaGetSymbolAddress((void**)&p_adjm,  g_adjmask);

    // stream fork for the independent protein branch
    cudaStream_t s2;
    cudaStreamCreateWithFlags(&s2, cudaStreamNonBlocking);
    cudaEvent_t evF, evJ;
    cudaEventCreateWithFlags(&evF, cudaEventDisableTiming);
    cudaEventCreateWithFlags(&evJ, cudaEventDisableTiming);

    // fused prep (both branches depend on it)
    k_prep<<<20901, 256>>>(adj, W_gat, W_go, conv_w, E_amino, atoms, E_atom);
    cudaEventRecord(evF, 0);
    cudaStreamWaitEvent(s2, evF, 0);

    // ---- protein branch (stream s2) ----
    k_conv1<<<dim3(LL, BB), 128, 0, s2>>>(amino, conv_b);
    k_conv<<<dim3(64, BB), 256, 0, s2>>>(p_cnvA, p_cnvB, conv_w + 121,   conv_b + 1);
    k_conv<<<dim3(64, BB), 256, 0, s2>>>(p_cnvB, p_cnvA, conv_w + 2*121, conv_b + 2);
    k_mm<1><<<dim3(256, 2), 256, 0, s2>>>(p_cnvA, W_att_w, W_att_b, p_cnvB, 16384, 128, 128);
    k_mean_part<<<dim3(8, BB), 128, 0, s2>>>(p_cnvB, amino_mask, p_pp2, p_pm2, LL);
    cudaEventRecord(evJ, s2);

    // ---- compound branch (default stream, concurrent) ----
    k_mm<0><<<dim3(128, 4), 256>>>(p_av, p_WcatT, nullptr, p_wh1, 8192, 256, 128);
    k_srcdst1<<<BB*NN_, 256>>>(a_gat);
    k_attn<1><<<dim3(4, 4, BB), 512>>>(p_wh1, p_src1, p_dst1, p_adjm, p_multi, 256);
    k_mm<0><<<dim3(128, 2), 256>>>(p_multi, p_WgoT, nullptr, p_wh2, 8192, 128, 256);
    k_srcdst2<<<BB*NN_, 128>>>(a_go);
    k_attn<0><<<dim3(4, 2, BB), 512>>>(p_wh2, p_src2, p_dst2, p_adjm, p_x, 128);
    k_mm<1><<<dim3(128, 2), 256>>>(p_x, W_comp_w, W_comp_b, p_atoms_vec, 8192, 128, 128);
    k_mm<1><<<dim3(128, 2), 256>>>(p_atoms_vec, W_att_w, W_att_b, p_av_att, 8192, 128, 128);
    k_mean_part<<<dim3(8, BB), 128>>>(p_av_att, atoms_mask, p_pp, p_pm, NN_);

    // ---- join + fused head ----
    cudaStreamWaitEvent(0, evJ, 0);
    k_final<<<BB, 256>>>(p_pp, p_pm, p_pp2, p_pm2, pred_w, pred_b, out);
}

// round 14
// speedup vs baseline: 1.7826x; 1.7826x over previous
#include <cuda_runtime.h>
#include <cuda_bf16.h>
#include <cuda_fp16.h>
#include <math.h>
#include <stdint.h>

// ---------------- constants ----------------
#define BB   16
#define NN_  512
#define LL   1024
#define CD   128
#define GD   64
#define NH   4
#define LAT  128

// ---------------- scratch ----------------
__device__ float g_av       [BB*NN_*CD];
__device__ float g_wh1      [BB*NN_*(GD*NH)];
__device__ float g_multi    [BB*NN_*(GD*NH)];
__device__ float g_wh2      [BB*NN_*CD];
__device__ float g_x        [BB*NN_*CD];
__device__ float g_atoms_vec[BB*NN_*LAT];
__device__ float g_av_att   [BB*NN_*LAT];
__device__ float g_cnvA[BB*LL*CD];
__device__ float g_cnvB[BB*LL*CD];
__device__ float g_T[30*11*CD];
__device__ float g_WcatT[256*128];
__device__ float g_WgoT [128*256];
__device__ float g_pp [BB*8*128];
__device__ float g_pm [BB*8];
__device__ float g_pp2[BB*8*128];
__device__ float g_pm2[BB*8];
__device__ uint32_t g_adjmask[BB*NN_*16];

__device__ __forceinline__ float lrelu(float x){ return x > 0.f ? x : 0.2f*x; }
__device__ __forceinline__ float eluf (float x){ return x > 0.f ? x : (__expf(x) - 1.f); }

// ---------------- f32x2 packed helpers (conv) ----------------
__device__ __forceinline__ uint64_t pk2(float x){
    uint32_t xi = __float_as_uint(x);
    uint64_t r; asm("mov.b64 %0, {%1, %1};" : "=l"(r) : "r"(xi)); return r;
}
__device__ __forceinline__ uint64_t pk2f(float x, float y){
    uint32_t xi = __float_as_uint(x), yi = __float_as_uint(y);
    uint64_t r; asm("mov.b64 %0, {%1, %2};" : "=l"(r) : "r"(xi), "r"(yi)); return r;
}
__device__ __forceinline__ void fma2(uint64_t& d, uint64_t a, uint64_t b){
    asm("fma.rn.f32x2 %0, %1, %2, %0;" : "+l"(d) : "l"(a), "l"(b));
}
__device__ __forceinline__ float2 up2(uint64_t v){
    uint32_t lo, hi; asm("mov.b64 {%0, %1}, %2;" : "=r"(lo), "=r"(hi) : "l"(v));
    return make_float2(__uint_as_float(lo), __uint_as_float(hi));
}

// ---------------- bf16 helpers (k_mm) ----------------
__device__ __forceinline__ void split2(float x, float y, uint32_t& hi, uint32_t& lo){
    __nv_bfloat162 h = __floats2bfloat162_rn(x, y);
    float hx = __bfloat162float(h.x), hy = __bfloat162float(h.y);
    __nv_bfloat162 l = __floats2bfloat162_rn(x - hx, y - hy);
    hi = *(uint32_t*)&h; lo = *(uint32_t*)&l;
}
__device__ __forceinline__ void mma16816(float* d, const uint32_t* a, const uint32_t* b){
    asm volatile(
        "mma.sync.aligned.m16n8k16.row.col.f32.bf16.bf16.f32 "
        "{%0,%1,%2,%3},{%4,%5,%6,%7},{%8,%9},{%0,%1,%2,%3};"
        : "+f"(d[0]), "+f"(d[1]), "+f"(d[2]), "+f"(d[3])
        : "r"(a[0]), "r"(a[1]), "r"(a[2]), "r"(a[3]), "r"(b[0]), "r"(b[1]));
}

// ---------------- fp16 helpers (attention) ----------------
__device__ __forceinline__ uint32_t packhf2(float x, float y){
    __half2 h = __floats2half2_rn(x, y);
    return *(uint32_t*)&h;
}
__device__ __forceinline__ uint32_t hadd2uh(uint32_t a, uint32_t b){
    __half2 r = __hadd2(*(__half2*)&a, *(__half2*)&b);
    return *(uint32_t*)&r;
}
__device__ __forceinline__ uint32_t hmul2uh(uint32_t a, uint32_t b){
    __half2 r = __hmul2(*(__half2*)&a, *(__half2*)&b);
    return *(uint32_t*)&r;
}
__device__ __forceinline__ float2 h2f2(uint32_t w){
    return __half22float2(*(__half2*)&w);
}
__device__ __forceinline__ void mma16816h(float* d, const uint32_t* a, const uint32_t* b){
    asm volatile(
        "mma.sync.aligned.m16n8k16.row.col.f32.f16.f16.f32 "
        "{%0,%1,%2,%3},{%4,%5,%6,%7},{%8,%9},{%0,%1,%2,%3};"
        : "+f"(d[0]), "+f"(d[1]), "+f"(d[2]), "+f"(d[3])
        : "r"(a[0]), "r"(a[1]), "r"(a[2]), "r"(a[3]), "r"(b[0]), "r"(b[1]));
}

// ---------------- fused prep kernel ----------------
__global__ void __launch_bounds__(256) k_prep(
    const int* __restrict__ adj, const float* __restrict__ W_gat,
    const float* __restrict__ W_go, const float* __restrict__ conv_w,
    const float* __restrict__ E_amino, const int* __restrict__ atoms,
    const float* __restrict__ E_atom)
{
    const int bid = blockIdx.x, tid = threadIdx.x;
    if (bid < 16384) {
        int t = bid*256 + tid;
        uint32_t bal = __ballot_sync(0xffffffffu, adj[t] > 0);
        if ((t & 31) == 0) g_adjmask[t >> 5] = bal;
    } else if (bid < 16512) {
        int idx = (bid - 16384)*256 + tid;
        int n = idx >> 7, k = idx & 127;
        int h = n >> 6, f = n & 63;
        g_WcatT[n*128 + k] = W_gat[((h*128) + k)*64 + f];
    } else if (bid < 16640) {
        int idx = (bid - 16512)*256 + tid;
        int n = idx >> 8, k = idx & 255;
        g_WgoT[n*256 + k] = W_go[k*128 + n];
    } else if (bid < 16805) {
        int idx = (bid - 16640)*256 + tid;
        if (idx < 42240) {
            int f = idx & 127, rest = idx >> 7;
            int dl = rest % 11, a = rest / 11;
            float acc = 0.f;
            #pragma unroll
            for (int df = 0; df < 11; ++df) {
                int fi = f + df - 5;
                if (fi >= 0 && fi < 128) acc += conv_w[dl*11 + df] * E_amino[a*128 + fi];
            }
            g_T[(a*11 + dl)*128 + f] = acc;
        }
    } else {
        int idx = (bid - 16805)*256 + tid;
        int row = idx >> 7, f = idx & 127;
        g_av[(size_t)row*128 + f] = E_atom[atoms[row]*128 + f];
    }
}

// ---------------- bf16-split tensor GEMM (64x64 tiles) ----------------
template<int ACT>
__global__ void __launch_bounds__(256) k_mm(
    const float* __restrict__ A, const float* __restrict__ BT,
    const float* __restrict__ bias, float* __restrict__ C,
    int M, int N, int K)
{
    __shared__ uint32_t Ah[2304], Al[2304], Bh[2304], Bl[2304];

    const int m0 = blockIdx.x*64, n0 = blockIdx.y*64;
    const int tid = threadIdx.x, w = tid >> 5, lane = tid & 31;
    const int wm = w & 3, wn = w >> 2;
    const int r4 = lane >> 2, cl = lane & 3;

    float acc[4][4];
    #pragma unroll
    for (int j = 0; j < 4; ++j)
        #pragma unroll
        for (int q = 0; q < 4; ++q) acc[j][q] = 0.f;

    for (int k0 = 0; k0 < K; k0 += 64) {
        __syncthreads();
        #pragma unroll
        for (int s = tid; s < 1024; s += 256) {
            int r = s >> 4, q = s & 15;
            float4 v = *(const float4*)&A[(size_t)(m0+r)*K + k0 + q*4];
            uint32_t h0,l0,h1,l1;
            split2(v.x, v.y, h0, l0); split2(v.z, v.w, h1, l1);
            int off = r*36 + q*2;
            Ah[off] = h0; Ah[off+1] = h1;
            Al[off] = l0; Al[off+1] = l1;
            float4 bv = *(const float4*)&BT[(size_t)(n0+r)*K + k0 + q*4];
            split2(bv.x, bv.y, h0, l0); split2(bv.z, bv.w, h1, l1);
            Bh[off] = h0; Bh[off+1] = h1;
            Bl[off] = l0; Bl[off+1] = l1;
        }
        __syncthreads();
        #pragma unroll
        for (int kk = 0; kk < 4; ++kk) {
            const int kw = kk*8;
            uint32_t ah[4], al[4];
            {
                int base = (wm*16 + r4)*36 + kw + cl;
                ah[0]=Ah[base];     ah[1]=Ah[base+288];
                ah[2]=Ah[base+4];   ah[3]=Ah[base+292];
                al[0]=Al[base];     al[1]=Al[base+288];
                al[2]=Al[base+4];   al[3]=Al[base+292];
            }
            uint32_t bh[4][2], bl[4][2];
            #pragma unroll
            for (int fn = 0; fn < 4; ++fn) {
                int base = (wn*32 + fn*8 + r4)*36 + kw + cl;
                bh[fn][0]=Bh[base]; bh[fn][1]=Bh[base+4];
                bl[fn][0]=Bl[base]; bl[fn][1]=Bl[base+4];
            }
            #pragma unroll
            for (int fn = 0; fn < 4; ++fn) {
                mma16816(acc[fn], ah, bh[fn]);
                mma16816(acc[fn], ah, bl[fn]);
                mma16816(acc[fn], al, bh[fn]);
            }
        }
    }
    #pragma unroll
    for (int fn = 0; fn < 4; ++fn) {
        int row = m0 + wm*16 + r4;
        int col = n0 + wn*32 + fn*8 + 2*cl;
        float b0 = 0.f, b1 = 0.f;
        if (bias) { b0 = bias[col]; b1 = bias[col+1]; }
        float v0 = acc[fn][0] + b0, v1 = acc[fn][1] + b1;
        float v2 = acc[fn][2] + b0, v3 = acc[fn][3] + b1;
        if (ACT) { v0=lrelu(v0); v1=lrelu(v1); v2=lrelu(v2); v3=lrelu(v3); }
        *(float2*)&C[(size_t)row*N + col]     = make_float2(v0, v1);
        *(float2*)&C[(size_t)(row+8)*N + col] = make_float2(v2, v3);
    }
}

// ---------------- GAT attention: fp16, fused src/dst dots, 512 threads ----------------
// MH=1: av=a_gat, head hy, AL=64, row slice at whoff. MH=0: av=a_go, AL=128, full row.
template<int MH>
__global__ void __launch_bounds__(512) k_attn(
    const float* __restrict__ wh, const float* __restrict__ av,
    const uint32_t* __restrict__ adjmask,
    float* __restrict__ out, int WS)
{
    __shared__ uint32_t Dp[256];
    __shared__ uint32_t PQ[512];
    __shared__ uint32_t sD2[128];
    __shared__ uint32_t sPQ[128];
    __shared__ float Sum[128], pst[512];     // pst doubles as dst scratch in prologue
    __shared__ uint32_t msk[2048];
    __shared__ uint32_t Ath[2304];
    __shared__ uint32_t Bh[1152], Bl[1152];

    const int it = blockIdx.x, hy = blockIdx.y, b = blockIdx.z;
    const int i0 = it*128;
    const int tid = threadIdx.x, w = tid >> 5, lane = tid & 31;
    const int r4 = lane >> 2, cl = lane & 3;
    const int whoff = hy*64;
    constexpr int AL = MH ? 64 : 128;
    const int doff = MH ? whoff : 0;

    const float* srcv = MH ? (av + hy*128)      : av;
    const float* dstv = MH ? (av + hy*128 + 64) : (av + 128);

    // dst_j for all 512 j (one per thread)
    {
        const float* wr = wh + (size_t)(b*512 + tid)*WS + doff;
        float dj = 0.f;
        #pragma unroll
        for (int k = 0; k < AL; k += 4) {
            float4 wv = *(const float4*)&wr[k];
            dj += wv.x*dstv[k] + wv.y*dstv[k+1] + wv.z*dstv[k+2] + wv.w*dstv[k+3];
        }
        pst[tid] = dj;
    }
    // src_i for this block's 128 rows
    if (tid < 128) {
        const float* wr = wh + (size_t)(b*512 + i0 + tid)*WS + doff;
        float s = 0.f;
        #pragma unroll
        for (int k = 0; k < AL; k += 4) {
            float4 wv = *(const float4*)&wr[k];
            s += wv.x*srcv[k] + wv.y*srcv[k+1] + wv.z*srcv[k+2] + wv.w*srcv[k+3];
        }
        sD2[tid] = packhf2(s, s);
        sPQ[tid] = packhf2(__expf(s), __expf(0.2f*s));
    }
    {
        const uint32_t* mb = adjmask + ((size_t)(b*512) + i0)*16;
        for (int s = tid; s < 2048; s += 512) msk[s] = mb[s];
    }
    __syncthreads();
    if (tid < 256) {
        float d0 = pst[2*tid], d1 = pst[2*tid + 1];
        Dp[tid] = packhf2(d0, d1);
        PQ[2*tid]     = packhf2(__expf(d0), __expf(0.2f*d0));
        PQ[2*tid + 1] = packhf2(__expf(d1), __expf(0.2f*d1));
    }

    const int wm = w & 3, wn = w >> 2;
    float acc[2][2][4];
    #pragma unroll
    for (int i = 0; i < 2; ++i)
        #pragma unroll
        for (int j = 0; j < 2; ++j)
            #pragma unroll
            for (int q = 0; q < 4; ++q) acc[i][j][q] = 0.f;

    const int ai = tid >> 2, qt = tid & 3;
    __syncthreads();
    const uint32_t si2 = sD2[ai], piq = sPQ[ai];
    float ps = 0.f;

    for (int c = 0; c < 16; ++c) {
        const int j0 = c*32;
        if (c) __syncthreads();
        {
            uint32_t mw = msk[ai*16 + c];
            #pragma unroll
            for (int jp = 0; jp < 4; ++jp) {
                int jl0 = qt*8 + jp*2, jl1 = jl0 + 1;
                uint32_t s2 = hadd2uh(si2, Dp[c*16 + qt*4 + jp]);
                uint32_t pr0 = hmul2uh(PQ[j0 + jl0], piq);
                uint32_t pr1 = hmul2uh(PQ[j0 + jl1], piq);
                uint32_t u0 = (s2 & 0x8000u)     ? (pr0 >> 16)          : (pr0 & 0xffffu);
                uint32_t u1 = (s2 & 0x80000000u) ? (pr1 & 0xffff0000u)  : (pr1 << 16);
                if (!((mw >> jl0) & 1u)) u0 = 0;
                if (!((mw >> jl1) & 1u)) u1 = 0;
                uint32_t word = u0 | u1;
                Ath[ai*18 + qt*4 + jp] = word;
                float2 f = h2f2(word);
                ps += f.x + f.y;
            }
        }
        {
            const int f = tid & 63, jg = tid >> 6;
            #pragma unroll
            for (int p = 0; p < 2; ++p) {
                int jl = jg*4 + p*2;
                float v0 = wh[(size_t)(b*512 + j0 + jl)*WS + whoff + f];
                float v1 = wh[(size_t)(b*512 + j0 + jl + 1)*WS + whoff + f];
                uint32_t hw = packhf2(v0, v1);
                float2 hv = h2f2(hw);
                uint32_t lw = packhf2(v0 - hv.x, v1 - hv.y);
                Bh[f*18 + jg*2 + p] = hw;
                Bl[f*18 + jg*2 + p] = lw;
            }
        }
        __syncthreads();
        #pragma unroll
        for (int kk = 0; kk < 2; ++kk) {
            const int kw = kk*8;
            uint32_t ah[2][4];
            #pragma unroll
            for (int fm = 0; fm < 2; ++fm) {
                int base = (wm*32 + fm*16 + r4)*18 + kw + cl;
                ah[fm][0]=Ath[base];     ah[fm][1]=Ath[base+144];
                ah[fm][2]=Ath[base+4];   ah[fm][3]=Ath[base+148];
            }
            uint32_t bh[2][2], bl[2][2];
            #pragma unroll
            for (int fn = 0; fn < 2; ++fn) {
                int base = (wn*16 + fn*8 + r4)*18 + kw + cl;
                bh[fn][0]=Bh[base]; bh[fn][1]=Bh[base+4];
                bl[fn][0]=Bl[base]; bl[fn][1]=Bl[base+4];
            }
            #pragma unroll
            for (int fm = 0; fm < 2; ++fm)
                #pragma unroll
                for (int fn = 0; fn < 2; ++fn) {
                    mma16816h(acc[fm][fn], ah[fm], bh[fn]);
                    mma16816h(acc[fm][fn], ah[fm], bl[fn]);
                }
        }
    }
    __syncthreads();
    pst[tid] = ps;
    __syncthreads();
    if (tid < 128)
        Sum[tid] = pst[4*tid] + pst[4*tid+1] + pst[4*tid+2] + pst[4*tid+3];
    __syncthreads();
    #pragma unroll
    for (int fm = 0; fm < 2; ++fm) {
        int rl = wm*32 + fm*16 + r4;
        float S0 = Sum[rl],   i0v = (S0 > 0.f) ? 1.f/S0 : 0.f;
        float S1 = Sum[rl+8], i1v = (S1 > 0.f) ? 1.f/S1 : 0.f;
        #pragma unroll
        for (int fn = 0; fn < 2; ++fn) {
            int col = whoff + wn*16 + fn*8 + 2*cl;
            float v0 = eluf(acc[fm][fn][0] * i0v);
            float v1 = eluf(acc[fm][fn][1] * i0v);
            float v2 = eluf(acc[fm][fn][2] * i1v);
            float v3 = eluf(acc[fm][fn][3] * i1v);
            *(float2*)&out[(size_t)(b*512 + i0 + rl)*WS + col]     = make_float2(v0, v1);
            *(float2*)&out[(size_t)(b*512 + i0 + rl + 8)*WS + col] = make_float2(v2, v3);
        }
    }
}

// ---------------- CNN ----------------
__global__ void k_conv1(const int* __restrict__ amino, const float* __restrict__ conv_b){
    const int l = blockIdx.x, b = blockIdx.y, f = threadIdx.x;
    float acc = conv_b[0];
    #pragma unroll
    for (int dl = 0; dl < 11; ++dl) {
        int l2 = l + dl - 5;
        if (l2 >= 0 && l2 < 1024) {
            int id = amino[b*1024 + l2];
            acc += g_T[((size_t)id*11 + dl)*128 + f];
        }
    }
    g_cnvA[((size_t)(b*1024) + l)*128 + f] = fmaxf(acc, 0.f);
}

// 11x11 SAME conv; sliding l-window (R10 proven version).
#define CONV_LOADROW(dstarr, trow) do {                                        \
    const float* _s = &tile[(trow)*140 + f0];                                  \
    _Pragma("unroll")                                                          \
    for (int _q = 0; _q < 4; ++_q) {                                           \
        float4 _v = *(const float4*)&_s[_q*4];                                 \
        dstarr[_q*4+0]=_v.x; dstarr[_q*4+1]=_v.y;                              \
        dstarr[_q*4+2]=_v.z; dstarr[_q*4+3]=_v.w;                              \
    }                                                                          \
} while(0)

#define CONV_STEP(Aarr, Barr, dl_) do {                                        \
    uint64_t vp[14];                                                           \
    _Pragma("unroll")                                                          \
    for (int _j = 0; _j < 14; ++_j) vp[_j] = pk2f(Aarr[_j], Barr[_j]);         \
    const float* _w = ws + (dl_)*11;                                           \
    _Pragma("unroll")                                                          \
    for (int _df = 0; _df < 11; ++_df) {                                       \
        uint64_t _wv = pk2(_w[_df]);                                           \
        fma2(acc[0], _wv, vp[_df+0]);                                          \
        fma2(acc[1], _wv, vp[_df+1]);                                          \
        fma2(acc[2], _wv, vp[_df+2]);                                          \
        fma2(acc[3], _wv, vp[_df+3]);                                          \
    }                                                                          \
} while(0)

__global__ void __launch_bounds__(256) k_conv(
    const float* __restrict__ in, float* __restrict__ out,
    const float* __restrict__ wsrc, const float* __restrict__ bsrc)
{
    __shared__ float tile[26*140];
    __shared__ float ws[121];
    const int lb = blockIdx.x * 16, b = blockIdx.y;
    const int tid = threadIdx.x;
    if (tid < 121) ws[tid] = wsrc[tid];
    for (int idx = tid; idx < 832; idx += 256) {          // 26 rows * 32 float4
        int r = idx >> 5, c4 = idx & 31;
        int gl = lb + r - 5;
        float4 v = make_float4(0.f, 0.f, 0.f, 0.f);
        if (gl >= 0 && gl < 1024)
            v = *(const float4*)&in[((size_t)(b*1024) + gl)*128 + c4*4];
        float* t = &tile[r*140 + 5 + c4*4];
        t[0]=v.x; t[1]=v.y; t[2]=v.z; t[3]=v.w;
    }
    for (int idx = tid; idx < 312; idx += 256) {          // border cols
        int r = idx / 12, c = idx % 12;
        tile[r*140 + (c < 5 ? c : 128 + c)] = 0.f;
    }
    __syncthreads();

    const int fg = tid >> 3, lg = tid & 7;
    const int f0 = fg * 4;
    const int rbase = lg * 2;

    float r0[16], r1[16];
    CONV_LOADROW(r0, rbase);
    CONV_LOADROW(r1, rbase + 1);

    uint64_t acc[4];
    {
        uint64_t bp = pk2(bsrc[0]);
        acc[0]=bp; acc[1]=bp; acc[2]=bp; acc[3]=bp;
    }
    #pragma unroll
    for (int dl = 0; dl < 11; ++dl) {
        if ((dl & 1) == 0) {
            CONV_STEP(r0, r1, dl);
            if (dl < 10) CONV_LOADROW(r0, rbase + dl + 2);
        } else {
            CONV_STEP(r1, r0, dl);
            if (dl < 10) CONV_LOADROW(r1, rbase + dl + 2);
        }
    }
    float* o0 = out + ((size_t)(b*1024) + lb + rbase)*128 + f0;
    float* o1 = o0 + 128;
    #pragma unroll
    for (int k = 0; k < 4; ++k) {
        float2 v = up2(acc[k]);
        o0[k] = fmaxf(v.x, 0.f);
        o1[k] = fmaxf(v.y, 0.f);
    }
}

// ---------------- masked mean pooling (partial) ----------------
__global__ void k_mean_part(const float* __restrict__ in, const float* __restrict__ mask,
                            float* __restrict__ pp, float* __restrict__ pm, int NNd){
    const int ch = blockIdx.x, b = blockIdx.y, f = threadIdx.x;
    const int rows = NNd / 8;
    const int r0 = ch * rows;
    float s = 0.f, m = 0.f;
    #pragma unroll 4
    for (int n = r0; n < r0 + rows; ++n) {
        float mk = mask[b*NNd + n];
        m += mk;
        s += mk * in[((size_t)b*NNd + n)*128 + f];
    }
    pp[(size_t)(b*8 + ch)*128 + f] = s;
    if (f == 0) pm[b*8 + ch] = m;
}

// ---------------- final predictor (fused mean-finalize + head) ----------------
__global__ void k_final(const float* __restrict__ pp,  const float* __restrict__ pm,
                        const float* __restrict__ pp2, const float* __restrict__ pm2,
                        const float* __restrict__ pred_w, const float* __restrict__ pred_b,
                        float* __restrict__ out){
    __shared__ float red[256];
    const int b = blockIdx.x, c = threadIdx.x;
    const float* P = (c < 128) ? pp  : pp2;
    const float* M = (c < 128) ? pm  : pm2;
    const int f = c & 127;
    float s = 0.f, m = 0.f;
    #pragma unroll
    for (int ch = 0; ch < 8; ++ch) {
        s += P[(size_t)(b*8 + ch)*128 + f];
        m += M[b*8 + ch];
    }
    float v = s / m;
    v = v > 0.f ? v : 0.04f*v;
    red[c] = v * pred_w[c];
    __syncthreads();
    for (int st = 128; st > 0; st >>= 1) {
        if (c < st) red[c] += red[c + st];
        __syncthreads();
    }
    if (c == 0) out[b] = red[0] + pred_b[0];
}

// ---------------- launch ----------------
extern "C" void kernel_launch(void* const* d_in, const int* in_sizes, int n_in,
                              void* d_out, int out_size)
{
    const int*   atoms      = (const int*)  d_in[0];
    const float* atoms_mask = (const float*)d_in[1];
    const int*   adj        = (const int*)  d_in[2];
    const int*   amino      = (const int*)  d_in[3];
    const float* amino_mask = (const float*)d_in[4];
    const float* E_atom     = (const float*)d_in[5];
    const float* E_amino    = (const float*)d_in[6];
    const float* W_gat      = (const float*)d_in[7];
    const float* a_gat      = (const float*)d_in[8];
    const float* W_go       = (const float*)d_in[9];
    const float* a_go       = (const float*)d_in[10];
    const float* W_comp_w   = (const float*)d_in[11];
    const float* W_comp_b   = (const float*)d_in[12];
    const float* conv_w     = (const float*)d_in[13];
    const float* conv_b     = (const float*)d_in[14];
    const float* W_att_w    = (const float*)d_in[15];
    const float* W_att_b    = (const float*)d_in[16];
    const float* pred_w     = (const float*)d_in[17];
    const float* pred_b     = (const float*)d_in[18];
    float* out = (float*)d_out;

    float *p_WcatT, *p_WgoT;
    float *p_av, *p_wh1, *p_multi, *p_wh2, *p_x, *p_atoms_vec, *p_av_att;
    float *p_cnvA, *p_cnvB;
    float *p_pp, *p_pm, *p_pp2, *p_pm2;
    uint32_t* p_adjm;
    cudaGetSymbolAddress((void**)&p_WcatT, g_WcatT);
    cudaGetSymbolAddress((void**)&p_WgoT,  g_WgoT);
    cudaGetSymbolAddress((void**)&p_av,    g_av);
    cudaGetSymbolAddress((void**)&p_wh1,   g_wh1);
    cudaGetSymbolAddress((void**)&p_multi, g_multi);
    cudaGetSymbolAddress((void**)&p_wh2,   g_wh2);
    cudaGetSymbolAddress((void**)&p_x,     g_x);
    cudaGetSymbolAddress((void**)&p_atoms_vec, g_atoms_vec);
    cudaGetSymbolAddress((void**)&p_av_att, g_av_att);
    cudaGetSymbolAddress((void**)&p_cnvA,  g_cnvA);
    cudaGetSymbolAddress((void**)&p_cnvB,  g_cnvB);
    cudaGetSymbolAddress((void**)&p_pp,    g_pp);
    cudaGetSymbolAddress((void**)&p_pm,    g_pm);
    cudaGetSymbolAddress((void**)&p_pp2,   g_pp2);
    cudaGetSymbolAddress((void**)&p_pm2,   g_pm2);
    cudaGetSymbolAddress((void**)&p_adjm,  g_adjmask);

    // stream fork for the independent protein branch
    cudaStream_t s2;
    cudaStreamCreateWithFlags(&s2, cudaStreamNonBlocking);
    cudaEvent_t evF, evJ;
    cudaEventCreateWithFlags(&evF, cudaEventDisableTiming);
    cudaEventCreateWithFlags(&evJ, cudaEventDisableTiming);

    // fused prep (both branches depend on it)
    k_prep<<<20901, 256>>>(adj, W_gat, W_go, conv_w, E_amino, atoms, E_atom);
    cudaEventRecord(evF, 0);
    cudaStreamWaitEvent(s2, evF, 0);

    // ---- protein branch (stream s2) ----
    k_conv1<<<dim3(LL, BB), 128, 0, s2>>>(amino, conv_b);
    k_conv<<<dim3(64, BB), 256, 0, s2>>>(p_cnvA, p_cnvB, conv_w + 121,   conv_b + 1);
    k_conv<<<dim3(64, BB), 256, 0, s2>>>(p_cnvB, p_cnvA, conv_w + 2*121, conv_b + 2);
    k_mm<1><<<dim3(256, 2), 256, 0, s2>>>(p_cnvA, W_att_w, W_att_b, p_cnvB, 16384, 128, 128);
    k_mean_part<<<dim3(8, BB), 128, 0, s2>>>(p_cnvB, amino_mask, p_pp2, p_pm2, LL);
    cudaEventRecord(evJ, s2);

    // ---- compound branch (default stream, concurrent) ----
    k_mm<0><<<dim3(128, 4), 256>>>(p_av, p_WcatT, nullptr, p_wh1, 8192, 256, 128);
    k_attn<1><<<dim3(4, 4, BB), 512>>>(p_wh1, a_gat, p_adjm, p_multi, 256);
    k_mm<0><<<dim3(128, 2), 256>>>(p_multi, p_WgoT, nullptr, p_wh2, 8192, 128, 256);
    k_attn<0><<<dim3(4, 2, BB), 512>>>(p_wh2, a_go, p_adjm, p_x, 128);
    k_mm<1><<<dim3(128, 2), 256>>>(p_x, W_comp_w, W_comp_b, p_atoms_vec, 8192, 128, 128);
    k_mm<1><<<dim3(128, 2), 256>>>(p_atoms_vec, W_att_w, W_att_b, p_av_att, 8192, 128, 128);
    k_mean_part<<<dim3(8, BB), 128>>>(p_av_att, atoms_mask, p_pp, p_pm, NN_);

    // ---- join + fused head ----
    cudaStreamWaitEvent(0, evJ, 0);
    k_final<<<BB, 256>>>(p_pp, p_pm, p_pp2, p_pm2, pred_w, pred_b, out);
}